// round 13
// baseline (speedup 1.0000x reference)
#include <cuda_runtime.h>
#include <cuda_bf16.h>
#include <math.h>
#include <stdint.h>

#define NUM_BINS     256
#define BITMAP_WORDS 2048
#define BITMAP_W64   1024
#define K1_BLOCKS    148             // 1 CTA/SM
#define K1_THREADS   1024
#define SMEM_BYTES   65536           // 256*256 occupancy byte map
#define R1_PT        4               // round-1: 4 float4-pairs per thread
#define N1_F4        (K1_BLOCKS * K1_THREADS * R1_PT)   // 606208 f4 = 2.42M samples

__device__ unsigned long long g_bitmap64[BITMAP_W64];   // zero at load; reset each run
__device__ unsigned int g_sync;                         // single arrival counter

// bits = RN(v*255 + 8388608.5f); 8388608.5f rounds to 8388608.0f, so
// bin = round_half_even(v*255) in [0,255] for v in [0,1). byte1 of bits = 0.
#define BIN_MAGIC 8388608.5f

__device__ __forceinline__ unsigned int bin_bits(float v)
{
    return __float_as_uint(fmaf(v, 255.0f, BIN_MAGIC));
}
__device__ __forceinline__ unsigned int pair_addr(float x, float y)
{
    return __byte_perm(bin_bits(x), bin_bits(y), 0x5504);   // binx<<8 | biny
}
__device__ __forceinline__ void mark4(unsigned char* occ, float4 x, float4 y)
{
    occ[pair_addr(x.x, y.x)] = 1;
    occ[pair_addr(x.y, y.y)] = 1;
    occ[pair_addr(x.z, y.z)] = 1;
    occ[pair_addr(x.w, y.w)] = 1;
}

// one word64 per thread; wsel staggers the address order across CTAs so the
// 148 CTAs' same-address atomic trains don't collide in lockstep.
__device__ __forceinline__ void pack_word(const unsigned char* occ, int w)
{
    const unsigned int* occ32 = reinterpret_cast<const unsigned int*>(occ);
    unsigned long long word = 0ull;
    #pragma unroll
    for (int k = 0; k < 16; ++k) {
        int k2 = (k + (w >> 1)) & 15;                    // bank-conflict-free gather
        unsigned int v = occ32[w * 16 + k2];             // bytes are exactly 0 or 1
        unsigned long long nib = (v | (v >> 7) | (v >> 14) | (v >> 21)) & 0xFu;
        word |= nib << (4 * k2);
    }
    if (word) atomicOr(&g_bitmap64[w], word);
}

extern "C" __global__ void __launch_bounds__(K1_THREADS, 1)
mi_fused(const float* __restrict__ X, const float* __restrict__ Y, int n,
         float* __restrict__ out)
{
    extern __shared__ unsigned char occ[];   // 65536 bytes
    __shared__ unsigned s_ticket;

    const int t = threadIdx.x;
    const int S = K1_BLOCKS * K1_THREADS;    // 151552
    const int n4 = n >> 2;
    const int n4_1 = (N1_F4 < n4) ? N1_F4 : n4;
    const float4* X4 = reinterpret_cast<const float4*>(X);
    const float4* Y4 = reinterpret_cast<const float4*>(Y);
    const int i0 = blockIdx.x * K1_THREADS + t;

    // ---- round-1 loads FIRST (latency hidden behind the smem zero) ----
    float4 x0, x1, x2, x3, y0, y1, y2, y3;
    const bool full4 = (i0 + 3 * S < n4_1);
    if (full4) {
        x0 = X4[i0];          y0 = Y4[i0];
        x1 = X4[i0 + S];      y1 = Y4[i0 + S];
        x2 = X4[i0 + 2 * S];  y2 = Y4[i0 + 2 * S];
        x3 = X4[i0 + 3 * S];  y3 = Y4[i0 + 3 * S];
    }

    // ---- zero shared occupancy map ----
    uint4* occ4 = reinterpret_cast<uint4*>(occ);
    #pragma unroll
    for (int i = t; i < SMEM_BYTES / 16; i += K1_THREADS)
        occ4[i] = make_uint4(0u, 0u, 0u, 0u);
    __syncthreads();

    // ---- round-1 marks ----
    if (full4) {
        mark4(occ, x0, y0); mark4(occ, x1, y1);
        mark4(occ, x2, y2); mark4(occ, x3, y3);
    } else {
        for (int i = i0; i < n4_1; i += S) {
            float4 x = X4[i], y = Y4[i];
            mark4(occ, x, y);
        }
    }
    if (blockIdx.x == 0) {              // scalar tail (n not multiple of 4)
        int tail = n & 3, base = n - tail;
        if (t < tail)
            occ[pair_addr(X[base + t], Y[base + t])] = 1;
    }
    __syncthreads();

    // ---- pack: exactly one word64 per thread, CTA-staggered order ----
    pack_word(occ, (t + (int)blockIdx.x * 5) & (BITMAP_W64 - 1));

    // ---- single arrival: merge barrier + ticket into ONE atomic ----
    __threadfence();                    // release this CTA's atomicOrs
    __syncthreads();
    if (t == 0) s_ticket = atomicAdd(&g_sync, 1u);
    __syncthreads();
    if (s_ticket != (unsigned)(K1_BLOCKS - 1)) return;   // 147 CTAs exit NOW

    // ================= last arriver only =================
    __threadfence();                    // acquire: all CTAs' ORs now visible

    unsigned long long have = __ldcg(&g_bitmap64[t]);
    if (__syncthreads_and(have == ~0ull)) {
        // All 65536 producible bins set -> every further mark is a no-op and
        // MI of the uniform occupancy map is closed-form:
        //   h = 1/65536; px = py = 1/256; mi = log(h/(px*py + 1e-10))
        g_bitmap64[t] = 0ull;           // reset for next graph replay
        if (t == 0) {
            const double h = 1.0 / 65536.0;
            out[0] = (float)(1.0 - tanh(log(h / (h + 1e-10))));
            g_sync = 0u;
        }
        return;
    }

    // ============ fallback: this single CTA computes exactly ============
    for (int i = n4_1 + t; i < n4; i += K1_THREADS) {
        float4 x = X4[i], y = Y4[i];
        mark4(occ, x, y);
    }
    __syncthreads();
    pack_word(occ, t);                  // re-merge (idempotent OR)
    __threadfence();
    __syncthreads();

    // full epilogue (all-float MI)
    unsigned int* sbm  = reinterpret_cast<unsigned int*>(occ);          // 8192 B
    int*          rowc = reinterpret_cast<int*>(occ + 8192);            // 1024 B
    float*        pyv  = reinterpret_cast<float*>(occ + 9216);          // 1024 B
    float*        part = reinterpret_cast<float*>(occ + 10240);         // 1024 B
    int*          sN   = reinterpret_cast<int*>(occ + 12288);

    __syncthreads();
    if (t == 0) *sN = 0;
    {
        unsigned int* g32 = reinterpret_cast<unsigned int*>(g_bitmap64);
        #pragma unroll
        for (int w = t; w < BITMAP_WORDS; w += K1_THREADS) {
            sbm[w] = __ldcg(&g32[w]);
            g32[w] = 0u;                // reset for next graph replay
        }
    }
    __syncthreads();

    unsigned int rw[8];
    if (t < NUM_BINS) {                 // thread t = row t
        int rc = 0;
        #pragma unroll
        for (int k = 0; k < 8; ++k) { rw[k] = sbm[t * 8 + k]; rc += __popc(rw[k]); }
        rowc[t] = rc;
        atomicAdd(sN, rc);
    }
    __syncthreads();

    const float invN = 1.0f / (float)(*sN);

    if (t < NUM_BINS) {                 // thread t = column t
        int wo = t >> 5, sh = t & 31;
        int cc = 0;
        #pragma unroll 8
        for (int bx = 0; bx < NUM_BINS; ++bx)
            cc += (sbm[bx * 8 + wo] >> sh) & 1;
        pyv[t] = (float)cc * invN;
    }
    __syncthreads();

    if (t < NUM_BINS) {                 // MI contribution of row t
        float pxf    = (float)rowc[t] * invN;
        float logInv = __logf(invN);
        float acc = 0.0f;
        #pragma unroll 8
        for (int j = 0; j < NUM_BINS; ++j) {
            if ((rw[j >> 5] >> (j & 31)) & 1u) {
                float d = fmaf(pxf, pyv[j], 1e-10f);
                acc += logInv - __logf(d);
            }
        }
        part[t] = acc * invN;
    }
    __syncthreads();

    for (int s = 128; s > 0; s >>= 1) {
        if (t < s) part[t] += part[t + s];
        __syncthreads();
    }
    if (t == 0) {
        out[0] = (float)(1.0 - tanh((double)part[0]));
        g_sync = 0u;
    }
}

extern "C" void kernel_launch(void* const* d_in, const int* in_sizes, int n_in,
                              void* d_out, int out_size)
{
    const float* X = (const float*)d_in[0];   // I_complementary
    const float* Y = (const float*)d_in[1];   // I_target
    float* out = (float*)d_out;
    int n = in_sizes[0];

    static bool attr_done = false;
    if (!attr_done) {
        cudaFuncSetAttribute(mi_fused, cudaFuncAttributeMaxDynamicSharedMemorySize,
                             SMEM_BYTES);
        attr_done = true;
    }
    mi_fused<<<K1_BLOCKS, K1_THREADS, SMEM_BYTES>>>(X, Y, n, out);
}

// round 16
// speedup vs baseline: 1.0173x; 1.0173x over previous
#include <cuda_runtime.h>
#include <cuda_bf16.h>
#include <math.h>
#include <stdint.h>

#define NUM_BINS     256
#define BITMAP_WORDS 2048
#define BITMAP_W64   1024
#define PAD          16              // one word64 per 128B L2 line
#define K1_BLOCKS    148             // 1 CTA/SM
#define K1_THREADS   1024
#define SMEM_BYTES   65536           // 256*256 occupancy byte map
#define R1_PT        4               // round-1: 4 float4-pairs per thread
#define N1_F4        (K1_BLOCKS * K1_THREADS * R1_PT)   // 606208 f4 = 2.42M samples

// padded: index w*PAD used, rest is spacing -> every atomic on its own L2 line
__device__ unsigned long long g_bm[BITMAP_W64 * PAD];   // 128KB, zero at load
__device__ unsigned int g_sync;                         // single arrival counter

// bits = RN(v*255 + 8388608.5f); 8388608.5f rounds to 8388608.0f, so
// bin = round_half_even(v*255) in [0,255] for v in [0,1). byte1 of bits = 0.
#define BIN_MAGIC 8388608.5f

__device__ __forceinline__ unsigned int bin_bits(float v)
{
    return __float_as_uint(fmaf(v, 255.0f, BIN_MAGIC));
}
__device__ __forceinline__ unsigned int pair_addr(float x, float y)
{
    return __byte_perm(bin_bits(x), bin_bits(y), 0x5504);   // binx<<8 | biny
}
__device__ __forceinline__ void mark4(unsigned char* occ, float4 x, float4 y)
{
    occ[pair_addr(x.x, y.x)] = 1;
    occ[pair_addr(x.y, y.y)] = 1;
    occ[pair_addr(x.z, y.z)] = 1;
    occ[pair_addr(x.w, y.w)] = 1;
}

// gather word64 w from the smem byte map (bank-conflict-free) and OR to global
__device__ __forceinline__ void pack_word(const unsigned char* occ, int w)
{
    const unsigned int* occ32 = reinterpret_cast<const unsigned int*>(occ);
    unsigned long long word = 0ull;
    #pragma unroll
    for (int k = 0; k < 16; ++k) {
        int k2 = (k + (w >> 1)) & 15;
        unsigned int v = occ32[w * 16 + k2];             // bytes are exactly 0 or 1
        unsigned long long nib = (v | (v >> 7) | (v >> 14) | (v >> 21)) & 0xFu;
        word |= nib << (4 * k2);
    }
    if (word) atomicOr(&g_bm[w * PAD], word);
}

extern "C" __global__ void __launch_bounds__(K1_THREADS, 1)
mi_fused(const float* __restrict__ X, const float* __restrict__ Y, int n,
         float* __restrict__ out)
{
    extern __shared__ unsigned char occ[];   // 65536 bytes
    __shared__ unsigned s_ticket;

    const int t = threadIdx.x;
    const int S = K1_BLOCKS * K1_THREADS;    // 151552
    const int n4 = n >> 2;
    const int n4_1 = (N1_F4 < n4) ? N1_F4 : n4;
    const float4* X4 = reinterpret_cast<const float4*>(X);
    const float4* Y4 = reinterpret_cast<const float4*>(Y);
    const int i0 = blockIdx.x * K1_THREADS + t;

    // ---- round-1 loads FIRST (latency hidden behind the smem zero) ----
    float4 x0, x1, x2, x3, y0, y1, y2, y3;
    const bool full4 = (i0 + 3 * S < n4_1);
    if (full4) {
        x0 = X4[i0];          y0 = Y4[i0];
        x1 = X4[i0 + S];      y1 = Y4[i0 + S];
        x2 = X4[i0 + 2 * S];  y2 = Y4[i0 + 2 * S];
        x3 = X4[i0 + 3 * S];  y3 = Y4[i0 + 3 * S];
    }

    // ---- zero shared occupancy map ----
    uint4* occ4 = reinterpret_cast<uint4*>(occ);
    #pragma unroll
    for (int i = t; i < SMEM_BYTES / 16; i += K1_THREADS)
        occ4[i] = make_uint4(0u, 0u, 0u, 0u);
    __syncthreads();

    // ---- round-1 marks ----
    if (full4) {
        mark4(occ, x0, y0); mark4(occ, x1, y1);
        mark4(occ, x2, y2); mark4(occ, x3, y3);
    } else {
        for (int i = i0; i < n4_1; i += S) {
            float4 x = X4[i], y = Y4[i];
            mark4(occ, x, y);
        }
    }
    if (blockIdx.x == 0) {              // scalar tail (n not multiple of 4)
        int tail = n & 3, base = n - tail;
        if (t < tail)
            occ[pair_addr(X[base + t], Y[base + t])] = 1;
    }
    __syncthreads();

    // ---- pack: one word64 per thread, CTA-staggered line order ----
    pack_word(occ, (t + (int)blockIdx.x * 7) & (BITMAP_W64 - 1));

    // ---- single arrival: barrier + ticket in ONE atomic ----
    __threadfence();                    // release this CTA's atomicOrs
    __syncthreads();
    if (t == 0) s_ticket = atomicAdd(&g_sync, 1u);
    __syncthreads();
    if (s_ticket != (unsigned)(K1_BLOCKS - 1)) return;   // 147 CTAs exit NOW

    // ================= last arriver only =================
    __threadfence();                    // acquire: all CTAs' ORs visible

    unsigned long long have = __ldcg(&g_bm[t * PAD]);
    if (__syncthreads_and(have == ~0ull)) {
        // All 65536 producible bins set -> further marks are no-ops; MI of the
        // uniform occupancy map is closed-form:
        //   h = 1/65536; px = py = 1/256; mi = log(h/(px*py + 1e-10))
        g_bm[t * PAD] = 0ull;           // reset for next graph replay
        if (t == 0) {
            const double h = 1.0 / 65536.0;
            out[0] = (float)(1.0 - tanh(log(h / (h + 1e-10))));
            g_sync = 0u;
        }
        return;
    }

    // ============ fallback: this single CTA computes exactly ============
    for (int i = n4_1 + t; i < n4; i += K1_THREADS) {
        float4 x = X4[i], y = Y4[i];
        mark4(occ, x, y);
    }
    __syncthreads();
    pack_word(occ, t);                  // re-merge (idempotent OR)
    __threadfence();
    __syncthreads();

    // full epilogue (all-float MI)
    unsigned int* sbm  = reinterpret_cast<unsigned int*>(occ);          // 8192 B
    int*          rowc = reinterpret_cast<int*>(occ + 8192);            // 1024 B
    float*        pyv  = reinterpret_cast<float*>(occ + 9216);          // 1024 B
    float*        part = reinterpret_cast<float*>(occ + 10240);         // 1024 B
    int*          sN   = reinterpret_cast<int*>(occ + 12288);

    __syncthreads();
    if (t == 0) *sN = 0;
    for (int w64 = t; w64 < BITMAP_W64; w64 += K1_THREADS) {
        unsigned long long v = __ldcg(&g_bm[w64 * PAD]);
        sbm[2 * w64]     = (unsigned int)v;
        sbm[2 * w64 + 1] = (unsigned int)(v >> 32);
        g_bm[w64 * PAD] = 0ull;         // reset for next graph replay
    }
    __syncthreads();

    unsigned int rw[8];
    if (t < NUM_BINS) {                 // thread t = row t
        int rc = 0;
        #pragma unroll
        for (int k = 0; k < 8; ++k) { rw[k] = sbm[t * 8 + k]; rc += __popc(rw[k]); }
        rowc[t] = rc;
        atomicAdd(sN, rc);
    }
    __syncthreads();

    const float invN = 1.0f / (float)(*sN);

    if (t < NUM_BINS) {                 // thread t = column t
        int wo = t >> 5, sh = t & 31;
        int cc = 0;
        #pragma unroll 8
        for (int bx = 0; bx < NUM_BINS; ++bx)
            cc += (sbm[bx * 8 + wo] >> sh) & 1;
        pyv[t] = (float)cc * invN;
    }
    __syncthreads();

    if (t < NUM_BINS) {                 // MI contribution of row t
        float pxf    = (float)rowc[t] * invN;
        float logInv = __logf(invN);
        float acc = 0.0f;
        #pragma unroll 8
        for (int j = 0; j < NUM_BINS; ++j) {
            if ((rw[j >> 5] >> (j & 31)) & 1u) {
                float d = fmaf(pxf, pyv[j], 1e-10f);
                acc += logInv - __logf(d);
            }
        }
        part[t] = acc * invN;
    }
    __syncthreads();

    for (int s = 128; s > 0; s >>= 1) {
        if (t < s) part[t] += part[t + s];
        __syncthreads();
    }
    if (t == 0) {
        out[0] = (float)(1.0 - tanh((double)part[0]));
        g_sync = 0u;
    }
}

extern "C" void kernel_launch(void* const* d_in, const int* in_sizes, int n_in,
                              void* d_out, int out_size)
{
    const float* X = (const float*)d_in[0];   // I_complementary
    const float* Y = (const float*)d_in[1];   // I_target
    float* out = (float*)d_out;
    int n = in_sizes[0];

    static bool attr_done = false;
    if (!attr_done) {
        cudaFuncSetAttribute(mi_fused, cudaFuncAttributeMaxDynamicSharedMemorySize,
                             SMEM_BYTES);
        attr_done = true;
    }
    mi_fused<<<K1_BLOCKS, K1_THREADS, SMEM_BYTES>>>(X, Y, n, out);
}